// round 1
// baseline (speedup 1.0000x reference)
#include <cuda_runtime.h>
#include <cuda_bf16.h>
#include <cstdint>

#define BB 4
#define S 8192
#define D 512
#define DFF 2048
#define NTOK (BB*S)
#define KSEL 1024
#define MAXSEL 4096

// ---------------- scratch (static device memory only; no allocs) ----------------
__device__ __nv_bfloat16 g_W1b[D*DFF];
__device__ __nv_bfloat16 g_W2b[DFF*D];
__device__ __nv_bfloat16 g_Xc[MAXSEL*D];
__device__ __nv_bfloat16 g_Hc[(size_t)MAXSEL*DFF];
__device__ float g_w[NTOK];
__device__ float g_thr[BB];
__device__ int   g_tok[MAXSEL];
__device__ float g_roww[MAXSEL];
__device__ int   g_nsel;

// ---------------- helpers ----------------
__device__ __forceinline__ unsigned f2u(float f) {
    unsigned u = __float_as_uint(f);
    return (u & 0x80000000u) ? ~u : (u | 0x80000000u);
}
__device__ __forceinline__ float u2f(unsigned u) {
    unsigned b = (u & 0x80000000u) ? (u & 0x7FFFFFFFu) : ~u;
    return __uint_as_float(b);
}
__device__ __forceinline__ float gelu_tanh(float v) {
    const float c = 0.7978845608028654f;  // sqrt(2/pi)
    float t = tanhf(c * (v + 0.044715f * v * v * v));
    return 0.5f * v * (1.0f + t);
}

// ---------------- 1) weight fp32->bf16 conversion ----------------
__global__ void convert_w(const float* __restrict__ W1, const float* __restrict__ W2) {
    int i = blockIdx.x * blockDim.x + threadIdx.x;
    const int n = D * DFF;
    if (i < n)            g_W1b[i]     = __float2bfloat16(W1[i]);
    else if (i < 2 * n)   g_W2b[i - n] = __float2bfloat16(W2[i - n]);
}

// ---------------- 2) router weights + out = x copy (fused single pass) ----------------
__global__ void router(const float* __restrict__ x, const float* __restrict__ Wr,
                       const float* __restrict__ br, float* __restrict__ out) {
    int warp = (blockIdx.x * blockDim.x + threadIdx.x) >> 5;   // one warp per token
    int lane = threadIdx.x & 31;
    if (warp >= NTOK) return;
    const float4* xr = (const float4*)(x + (size_t)warp * D);
    float4* orow = (float4*)(out + (size_t)warp * D);
    const float4* wr = (const float4*)Wr;
    float acc = 0.f;
#pragma unroll
    for (int i = 0; i < D / 128; ++i) {   // 4 iterations of 32 lanes * float4
        float4 v = xr[lane + i * 32];
        float4 w = __ldg(&wr[lane + i * 32]);
        orow[lane + i * 32] = v;
        acc += v.x * w.x + v.y * w.y + v.z * w.z + v.w * w.w;
    }
#pragma unroll
    for (int o = 16; o; o >>= 1) acc += __shfl_xor_sync(0xFFFFFFFFu, acc, o);
    if (lane == 0) g_w[warp] = acc + br[0];
}

// ---------------- 3) exact k-th largest per batch (radix select) ----------------
__global__ void kselect() {
    int b = blockIdx.x;
    int tid = threadIdx.x;   // 256 threads
    __shared__ unsigned hist[256];
    __shared__ unsigned sh_prefix;
    __shared__ int sh_rank;
    if (tid == 0) {
        sh_prefix = 0u;
        sh_rank = S - KSEL;          // ascending rank 7168 == k-th largest
        if (b == 0) g_nsel = 0;      // reset compaction counter each replay
    }
    __syncthreads();
    for (int p = 3; p >= 0; --p) {
        hist[tid] = 0u;
        __syncthreads();
        unsigned prefix = sh_prefix;
        unsigned hi_mask = (p == 3) ? 0u : (0xFFFFFFFFu << ((p + 1) * 8));
        for (int i = tid; i < S; i += 256) {
            unsigned key = f2u(g_w[b * S + i]);
            if ((key & hi_mask) == prefix)
                atomicAdd(&hist[(key >> (p * 8)) & 0xFFu], 1u);
        }
        __syncthreads();
        if (tid == 0) {
            int rank = sh_rank;
            unsigned cum = 0;
            for (int bin = 0; bin < 256; ++bin) {
                unsigned c = hist[bin];
                if ((unsigned)rank < cum + c) {
                    sh_prefix = prefix | ((unsigned)bin << (p * 8));
                    sh_rank = rank - (int)cum;
                    break;
                }
                cum += c;
            }
        }
        __syncthreads();
    }
    if (tid == 0) g_thr[b] = u2f(sh_prefix);
}

// ---------------- 4) compact selected tokens: gather x rows -> bf16 ----------------
__global__ void compact(const float* __restrict__ x) {
    int t = blockIdx.x;               // one 128-thread block per token
    int b = t / S;
    float w = g_w[t];
    if (!(w > g_thr[b])) return;      // strict >, matches reference mask
    __shared__ int slot;
    if (threadIdx.x == 0) slot = atomicAdd(&g_nsel, 1);
    __syncthreads();
    int r = slot;
    if (threadIdx.x == 0) { g_tok[r] = t; g_roww[r] = w; }
    float4 v = ((const float4*)(x + (size_t)t * D))[threadIdx.x];
    __nv_bfloat162* d2 = (__nv_bfloat162*)(g_Xc + (size_t)r * D) + threadIdx.x * 2;
    d2[0] = __floats2bfloat162_rn(v.x, v.y);
    d2[1] = __floats2bfloat162_rn(v.z, v.w);
}

// ---------------- 5) bf16 mma GEMM, block 64x128, warp 32x32, K-step 32 ----------------
// EPI==1: Hc = gelu(Xc @ W1 + b1)   (K=512,  N=2048)
// EPI==2: out[tok] = (Hc @ W2 + b2) * roww   (K=2048, N=512, scattered)
template <int K, int N, int EPI>
__global__ __launch_bounds__(256) void gemm_kern(const float* __restrict__ bias,
                                                 float* __restrict__ out) {
    int nsel = g_nsel;
    int m0 = blockIdx.y * 64;
    if (m0 >= nsel) return;
    int n0 = blockIdx.x * 128;

    const __nv_bfloat16* __restrict__ Ag = (EPI == 1) ? g_Xc : g_Hc;
    const __nv_bfloat16* __restrict__ Bg = (EPI == 1) ? g_W1b : g_W2b;

    __shared__ __nv_bfloat16 sA[64][40];    // 80B row stride: conflict-free ldmatrix
    __shared__ __nv_bfloat16 sB[32][136];   // 272B row stride

    int tid = threadIdx.x;
    int lane = tid & 31, w = tid >> 5;
    int wm = w >> 2, wn = w & 3;            // 2 x 4 warp grid

    float acc[2][4][4];
#pragma unroll
    for (int mi = 0; mi < 2; mi++)
#pragma unroll
        for (int ni = 0; ni < 4; ni++)
#pragma unroll
            for (int c = 0; c < 4; c++) acc[mi][ni][c] = 0.f;

    int arow = tid >> 2, acol = (tid & 3) * 8;     // A: 64 x 32, 16B each
    int brow = tid >> 4, bcol = (tid & 15) * 8;    // B: 32 x 128, 2 x 16B each

    for (int k0 = 0; k0 < K; k0 += 32) {
        uint4 av  = *(const uint4*)(Ag + (size_t)(m0 + arow) * K + k0 + acol);
        uint4 bv0 = *(const uint4*)(Bg + (size_t)(k0 + brow) * N + n0 + bcol);
        uint4 bv1 = *(const uint4*)(Bg + (size_t)(k0 + brow + 16) * N + n0 + bcol);
        *(uint4*)&sA[arow][acol] = av;
        *(uint4*)&sB[brow][bcol] = bv0;
        *(uint4*)&sB[brow + 16][bcol] = bv1;
        __syncthreads();
#pragma unroll
        for (int kk = 0; kk < 32; kk += 16) {
            unsigned a[2][4], bf[4][2];
#pragma unroll
            for (int mi = 0; mi < 2; mi++) {
                unsigned addr = (unsigned)__cvta_generic_to_shared(
                    &sA[wm * 32 + mi * 16 + (lane & 15)][kk + (lane >> 4) * 8]);
                asm volatile("ldmatrix.sync.aligned.m8n8.x4.shared.b16 {%0,%1,%2,%3}, [%4];"
                             : "=r"(a[mi][0]), "=r"(a[mi][1]), "=r"(a[mi][2]), "=r"(a[mi][3])
                             : "r"(addr));
            }
#pragma unroll
            for (int ni = 0; ni < 4; ni++) {
                unsigned addr = (unsigned)__cvta_generic_to_shared(
                    &sB[kk + (lane & 15)][wn * 32 + ni * 8]);
                asm volatile("ldmatrix.sync.aligned.m8n8.x2.trans.shared.b16 {%0,%1}, [%2];"
                             : "=r"(bf[ni][0]), "=r"(bf[ni][1])
                             : "r"(addr));
            }
#pragma unroll
            for (int mi = 0; mi < 2; mi++)
#pragma unroll
                for (int ni = 0; ni < 4; ni++)
                    asm volatile(
                        "mma.sync.aligned.m16n8k16.row.col.f32.bf16.bf16.f32 "
                        "{%0,%1,%2,%3}, {%4,%5,%6,%7}, {%8,%9}, {%0,%1,%2,%3};"
                        : "+f"(acc[mi][ni][0]), "+f"(acc[mi][ni][1]),
                          "+f"(acc[mi][ni][2]), "+f"(acc[mi][ni][3])
                        : "r"(a[mi][0]), "r"(a[mi][1]), "r"(a[mi][2]), "r"(a[mi][3]),
                          "r"(bf[ni][0]), "r"(bf[ni][1]));
        }
        __syncthreads();
    }

    // epilogue
    int g = lane >> 2, tg = lane & 3;
#pragma unroll
    for (int mi = 0; mi < 2; mi++)
#pragma unroll
        for (int ci = 0; ci < 2; ci++) {
            int row = m0 + wm * 32 + mi * 16 + g + ci * 8;
            if (row >= nsel) continue;
#pragma unroll
            for (int ni = 0; ni < 4; ni++) {
                int col = n0 + wn * 32 + ni * 8 + tg * 2;
                float v0 = acc[mi][ni][ci * 2 + 0] + bias[col];
                float v1 = acc[mi][ni][ci * 2 + 1] + bias[col + 1];
                if (EPI == 1) {
                    v0 = gelu_tanh(v0);
                    v1 = gelu_tanh(v1);
                    *(__nv_bfloat162*)(g_Hc + (size_t)row * DFF + col) =
                        __floats2bfloat162_rn(v0, v1);
                } else {
                    int t = g_tok[row];
                    float sc = g_roww[row];
                    float2 o;
                    o.x = v0 * sc;
                    o.y = v1 * sc;
                    *(float2*)(out + (size_t)t * D + col) = o;
                }
            }
        }
}

// ---------------- launch ----------------
extern "C" void kernel_launch(void* const* d_in, const int* in_sizes, int n_in,
                              void* d_out, int out_size) {
    const float* x  = (const float*)d_in[0];
    // d_in[1] = position_ids (int64) — unused by the reference math
    const float* Wr = (const float*)d_in[2];
    const float* br = (const float*)d_in[3];
    const float* W1 = (const float*)d_in[4];
    const float* b1 = (const float*)d_in[5];
    const float* W2 = (const float*)d_in[6];
    const float* b2 = (const float*)d_in[7];
    float* out = (float*)d_out;

    convert_w<<<(2 * D * DFF + 255) / 256, 256>>>(W1, W2);
    router<<<NTOK / 8, 256>>>(x, Wr, br, out);
    kselect<<<BB, 256>>>();
    compact<<<NTOK, 128>>>(x);
    gemm_kern<512, 2048, 1><<<dim3(DFF / 128, MAXSEL / 64), 256>>>(b1, nullptr);
    gemm_kern<2048, 512, 2><<<dim3(D / 128, MAXSEL / 64), 256>>>(b2, out);
}

// round 4
// speedup vs baseline: 1.2418x; 1.2418x over previous
#include <cuda_runtime.h>
#include <cuda_bf16.h>
#include <cstdint>

#define BB 4
#define S 8192
#define D 512
#define DFF 2048
#define NTOK (BB*S)
#define KSEL 1024
#define MAXSEL 4096

// ---------------- scratch (static device memory only; no allocs) ----------------
__device__ __nv_bfloat16 g_W1b[D*DFF];
__device__ __nv_bfloat16 g_W2b[DFF*D];
__device__ __nv_bfloat16 g_Xc[MAXSEL*D];
__device__ __nv_bfloat16 g_Hc[(size_t)MAXSEL*DFF];
__device__ float g_w[NTOK];
__device__ float g_thr[BB];
__device__ int   g_tok[MAXSEL];
__device__ float g_roww[MAXSEL];
__device__ int   g_nsel;

// ---------------- helpers ----------------
__device__ __forceinline__ unsigned f2u(float f) {
    unsigned u = __float_as_uint(f);
    return (u & 0x80000000u) ? ~u : (u | 0x80000000u);
}
__device__ __forceinline__ float u2f(unsigned u) {
    unsigned b = (u & 0x80000000u) ? (u & 0x7FFFFFFFu) : ~u;
    return __uint_as_float(b);
}
__device__ __forceinline__ float gelu_tanh(float v) {
    const float c = 0.7978845608028654f;  // sqrt(2/pi)
    float t = tanhf(c * (v + 0.044715f * v * v * v));
    return 0.5f * v * (1.0f + t);
}
__device__ __forceinline__ void cp_async16(void* smem, const void* gmem) {
    unsigned s = (unsigned)__cvta_generic_to_shared(smem);
    asm volatile("cp.async.cg.shared.global [%0], [%1], 16;\n" :: "r"(s), "l"(gmem));
}

// ---------------- 1) weight fp32->bf16 conversion ----------------
__global__ void convert_w(const float* __restrict__ W1, const float* __restrict__ W2) {
    int i = blockIdx.x * blockDim.x + threadIdx.x;
    const int n = D * DFF;
    if (i < n)            g_W1b[i]     = __float2bfloat16(W1[i]);
    else if (i < 2 * n)   g_W2b[i - n] = __float2bfloat16(W2[i - n]);
}

// ---------------- 2) router weights + out = x copy (fused single pass) ----------------
__global__ void router(const float* __restrict__ x, const float* __restrict__ Wr,
                       const float* __restrict__ br, float* __restrict__ out) {
    int warp = (blockIdx.x * blockDim.x + threadIdx.x) >> 5;   // one warp per token
    int lane = threadIdx.x & 31;
    if (warp >= NTOK) return;
    const float4* xr = (const float4*)(x + (size_t)warp * D);
    float4* orow = (float4*)(out + (size_t)warp * D);
    const float4* wr = (const float4*)Wr;
    float acc = 0.f;
#pragma unroll
    for (int i = 0; i < D / 128; ++i) {   // 4 iterations of 32 lanes * float4
        float4 v = xr[lane + i * 32];
        float4 w = __ldg(&wr[lane + i * 32]);
        orow[lane + i * 32] = v;
        acc += v.x * w.x + v.y * w.y + v.z * w.z + v.w * w.w;
    }
#pragma unroll
    for (int o = 16; o; o >>= 1) acc += __shfl_xor_sync(0xFFFFFFFFu, acc, o);
    if (lane == 0) g_w[warp] = acc + br[0];
}

// ---------------- 3) exact k-th largest per batch (smem radix select) ----------------
__global__ __launch_bounds__(512) void kselect() {
    __shared__ unsigned keys[S];       // 32KB: all router keys for this batch
    __shared__ unsigned hist[256];
    __shared__ unsigned scn[256];
    __shared__ unsigned sh_prefix;
    __shared__ int sh_rank;
    int b = blockIdx.x;
    int tid = threadIdx.x;             // 512 threads
    for (int i = tid; i < S; i += 512) keys[i] = f2u(g_w[b * S + i]);
    if (tid == 0) {
        sh_prefix = 0u;
        sh_rank = S - KSEL;            // ascending rank of k-th largest
        if (b == 0) g_nsel = 0;        // reset compaction counter each replay
    }
    __syncthreads();
#pragma unroll
    for (int p = 3; p >= 0; --p) {
        if (tid < 256) hist[tid] = 0u;
        __syncthreads();
        unsigned prefix = sh_prefix;
        unsigned hi_mask = (p == 3) ? 0u : (0xFFFFFFFFu << ((p + 1) * 8));
        for (int i = tid; i < S; i += 512) {
            unsigned k = keys[i];
            if ((k & hi_mask) == prefix)
                atomicAdd(&hist[(k >> (p * 8)) & 0xFFu], 1u);
        }
        __syncthreads();
        if (tid < 256) scn[tid] = hist[tid];
        __syncthreads();
        for (int off = 1; off < 256; off <<= 1) {      // Hillis-Steele inclusive scan
            unsigned v = 0;
            if (tid < 256) { v = scn[tid]; if (tid >= off) v += scn[tid - off]; }
            __syncthreads();
            if (tid < 256) scn[tid] = v;
            __syncthreads();
        }
        int rank = sh_rank;
        __syncthreads();
        if (tid < 256) {
            unsigned incl = scn[tid], excl = incl - hist[tid];
            if ((unsigned)rank >= excl && (unsigned)rank < incl) {   // unique winner
                sh_prefix = prefix | ((unsigned)tid << (p * 8));
                sh_rank = rank - (int)excl;
            }
        }
        __syncthreads();
    }
    if (tid == 0) g_thr[b] = u2f(sh_prefix);
}

// ---------------- 4a) build compacted index list (warp-aggregated) ----------------
__global__ void build_index() {
    int t = blockIdx.x * blockDim.x + threadIdx.x;   // dense, NTOK threads
    float w = g_w[t];
    int b = t >> 13;                                  // t / S
    bool sel = (w > g_thr[b]);                        // strict >, matches reference
    unsigned m = __ballot_sync(0xFFFFFFFFu, sel);
    int lane = threadIdx.x & 31;
    int leader = __ffs(m) - 1;
    int base = 0;
    if (m && lane == leader) base = atomicAdd(&g_nsel, __popc(m));
    if (m) base = __shfl_sync(0xFFFFFFFFu, base, leader);
    if (sel) {
        int r = base + __popc(m & ((1u << lane) - 1u));
        g_tok[r] = t;
        g_roww[r] = w;
    }
}

// ---------------- 4b) gather selected x rows -> bf16 ----------------
__global__ void gather_rows(const float* __restrict__ x) {
    int r = blockIdx.x;                  // one 128-thread block per selected row
    if (r >= g_nsel) return;
    int t = g_tok[r];
    float4 v = ((const float4*)(x + (size_t)t * D))[threadIdx.x];
    __nv_bfloat162* d2 = (__nv_bfloat162*)(g_Xc + (size_t)r * D) + threadIdx.x * 2;
    d2[0] = __floats2bfloat162_rn(v.x, v.y);
    d2[1] = __floats2bfloat162_rn(v.z, v.w);
}

// ---------------- 5) bf16 mma GEMM, block 128x128x32, 8 warps, cp.async 2-stage ----
// EPI==1: Hc = gelu(Xc @ W1 + b1)   (K=512,  N=2048)
// EPI==2: out[tok] = (Hc @ W2 + b2) * roww   (K=2048, N=512, scattered)
template <int K, int N, int EPI>
__global__ __launch_bounds__(256, 2) void gemm_kern(const float* __restrict__ bias,
                                                    float* __restrict__ out) {
    int nsel = g_nsel;
    int m0 = blockIdx.y * 128;
    if (m0 >= nsel) return;
    int n0 = blockIdx.x * 128;

    const __nv_bfloat16* __restrict__ Ag = (EPI == 1) ? g_Xc : g_Hc;
    const __nv_bfloat16* __restrict__ Bg = (EPI == 1) ? g_W1b : g_W2b;

    __shared__ __nv_bfloat16 sA[2][128][40];    // 80B row stride (conflict-free)
    __shared__ __nv_bfloat16 sB[2][32][136];    // 272B row stride (conflict-free)

    int tid = threadIdx.x;
    int lane = tid & 31, w = tid >> 5;
    int wm = w >> 2, wn = w & 3;                // 2 x 4 warp grid, warp tile 64x32

    float acc[4][4][4] = {};

    // stage loader: A = 128x32 (512 x 16B), B = 32x128 (512 x 16B); 2 chunks each/thread
    auto load_stage = [&](int st, int k0) {
#pragma unroll
        for (int i = 0; i < 2; i++) {
            int c = tid + i * 256;
            int r = c >> 2, col = (c & 3) * 8;
            cp_async16(&sA[st][r][col], Ag + (size_t)(m0 + r) * K + (k0 + col));
        }
#pragma unroll
        for (int i = 0; i < 2; i++) {
            int c = tid + i * 256;
            int r = c >> 4, col = (c & 15) * 8;
            cp_async16(&sB[st][r][col], Bg + (size_t)(k0 + r) * N + (n0 + col));
        }
        asm volatile("cp.async.commit_group;\n");
    };

    constexpr int T = K / 32;
    load_stage(0, 0);
    for (int it = 0; it < T; ++it) {
        if (it + 1 < T) {
            load_stage((it + 1) & 1, (it + 1) * 32);
            asm volatile("cp.async.wait_group 1;\n" ::: "memory");
        } else {
            asm volatile("cp.async.wait_group 0;\n" ::: "memory");
        }
        __syncthreads();
        int st = it & 1;
#pragma unroll
        for (int kk = 0; kk < 32; kk += 16) {
            unsigned a[4][4], bfr[4][2];
#pragma unroll
            for (int mi = 0; mi < 4; mi++) {
                unsigned addr = (unsigned)__cvta_generic_to_shared(
                    &sA[st][wm * 64 + mi * 16 + (lane & 15)][kk + (lane >> 4) * 8]);
                asm volatile("ldmatrix.sync.aligned.m8n8.x4.shared.b16 {%0,%1,%2,%3}, [%4];"
                             : "=r"(a[mi][0]), "=r"(a[mi][1]), "=r"(a[mi][2]), "=r"(a[mi][3])
                             : "r"(addr));
            }
#pragma unroll
            for (int ni = 0; ni < 4; ni++) {
                unsigned addr = (unsigned)__cvta_generic_to_shared(
                    &sB[st][kk + (lane & 15)][wn * 32 + ni * 8]);
                asm volatile("ldmatrix.sync.aligned.m8n8.x2.trans.shared.b16 {%0,%1}, [%2];"
                             : "=r"(bfr[ni][0]), "=r"(bfr[ni][1])
                             : "r"(addr));
            }
#pragma unroll
            for (int mi = 0; mi < 4; mi++)
#pragma unroll
                for (int ni = 0; ni < 4; ni++)
                    asm volatile(
                        "mma.sync.aligned.m16n8k16.row.col.f32.bf16.bf16.f32 "
                        "{%0,%1,%2,%3}, {%4,%5,%6,%7}, {%8,%9}, {%0,%1,%2,%3};"
                        : "+f"(acc[mi][ni][0]), "+f"(acc[mi][ni][1]),
                          "+f"(acc[mi][ni][2]), "+f"(acc[mi][ni][3])
                        : "r"(a[mi][0]), "r"(a[mi][1]), "r"(a[mi][2]), "r"(a[mi][3]),
                          "r"(bfr[ni][0]), "r"(bfr[ni][1]));
        }
        __syncthreads();
    }

    // epilogue
    int g = lane >> 2, tg = lane & 3;
#pragma unroll
    for (int mi = 0; mi < 4; mi++)
#pragma unroll
        for (int ci = 0; ci < 2; ci++) {
            int row = m0 + wm * 64 + mi * 16 + g + ci * 8;
            if (row >= nsel) continue;
#pragma unroll
            for (int ni = 0; ni < 4; ni++) {
                int col = n0 + wn * 32 + ni * 8 + tg * 2;
                float v0 = acc[mi][ni][ci * 2 + 0] + bias[col];
                float v1 = acc[mi][ni][ci * 2 + 1] + bias[col + 1];
                if (EPI == 1) {
                    v0 = gelu_tanh(v0);
                    v1 = gelu_tanh(v1);
                    *(__nv_bfloat162*)(g_Hc + (size_t)row * DFF + col) =
                        __floats2bfloat162_rn(v0, v1);
                } else {
                    int t = g_tok[row];
                    float sc = g_roww[row];
                    float2 o;
                    o.x = v0 * sc;
                    o.y = v1 * sc;
                    *(float2*)(out + (size_t)t * D + col) = o;
                }
            }
        }
}

// ---------------- launch ----------------
extern "C" void kernel_launch(void* const* d_in, const int* in_sizes, int n_in,
                              void* d_out, int out_size) {
    const float* x  = (const float*)d_in[0];
    // d_in[1] = position_ids (int64) — unused by the reference math
    const float* Wr = (const float*)d_in[2];
    const float* br = (const float*)d_in[3];
    const float* W1 = (const float*)d_in[4];
    const float* b1 = (const float*)d_in[5];
    const float* W2 = (const float*)d_in[6];
    const float* b2 = (const float*)d_in[7];
    float* out = (float*)d_out;

    convert_w<<<(2 * D * DFF + 255) / 256, 256>>>(W1, W2);
    router<<<NTOK / 8, 256>>>(x, Wr, br, out);
    kselect<<<BB, 512>>>();
    build_index<<<NTOK / 256, 256>>>();
    gather_rows<<<MAXSEL, 128>>>(x);
    gemm_kern<512, 2048, 1><<<dim3(DFF / 128, MAXSEL / 128), 256>>>(b1, nullptr);
    gemm_kern<2048, 512, 2><<<dim3(D / 128, MAXSEL / 128), 256>>>(b2, out);
}